// round 13
// baseline (speedup 1.0000x reference)
#include <cuda_runtime.h>
#include <cuda_fp16.h>
#include <cstdint>
#include <cstddef>

// Problem constants (B=16, H=W=56, C=1024, K=150, WS=7)
#define M_ROWS 50176
#define CDIM   1024
#define KSEM   150
#define NWIN   1024
#define BATCH_STRIDE 3136

// -------- scratch (device globals) --------
__device__ __half g_xnh [(size_t)M_ROWS * CDIM];   // LN out half
__device__ __half g_semh[(size_t)M_ROWS * 160];    // seg_map half, padded stride
__device__ __half g_kfh [(size_t)M_ROWS * 160];    // seg_ft half, padded stride
__device__ __half g_aoh [(size_t)M_ROWS * CDIM];   // attention out half
__device__ __half g_wqkh[(size_t)300 * CDIM];      // wq(150) + wk(150) stacked
__device__ __half g_wrh [(size_t)CDIM * CDIM];     // wr half
__device__ __half g_wvth[(size_t)CDIM * CDIM];     // wv^T half
__device__ __half g_wch [(size_t)CDIM * CDIM];     // Wc = gamma * Wr @ Wv, half
__device__ float  g_bvr [CDIM];                    // gamma * (Wr @ bv + br)

__device__ __forceinline__ uint32_t smem_to_u32(const void* p) {
    uint32_t a;
    asm("{ .reg .u64 t; cvta.to.shared.u64 t, %1; cvt.u32.u64 %0, t; }" : "=r"(a) : "l"(p));
    return a;
}
#define CP_ASYNC16(dst, src) \
    asm volatile("cp.async.cg.shared.global [%0], [%1], 16;" :: "r"(dst), "l"(src) : "memory")
#define CP_COMMIT() asm volatile("cp.async.commit_group;" ::: "memory")
#define LDMATRIX_X4(r0, r1, r2, r3, addr) \
    asm volatile("ldmatrix.sync.aligned.m8n8.x4.shared.b16 {%0,%1,%2,%3}, [%4];" \
        : "=r"(r0), "=r"(r1), "=r"(r2), "=r"(r3) : "r"(addr))
#define LDMATRIX_X4_T(r0, r1, r2, r3, addr) \
    asm volatile("ldmatrix.sync.aligned.m8n8.x4.trans.shared.b16 {%0,%1,%2,%3}, [%4];" \
        : "=r"(r0), "=r"(r1), "=r"(r2), "=r"(r3) : "r"(addr))
#define MMA16816(acc, a, b0, b1) \
    asm volatile("mma.sync.aligned.m16n8k16.row.col.f32.f16.f16.f32 " \
        "{%0,%1,%2,%3}, {%4,%5,%6,%7}, {%8,%9}, {%0,%1,%2,%3};" \
        : "+f"((acc)[0]), "+f"((acc)[1]), "+f"((acc)[2]), "+f"((acc)[3]) \
        : "r"((a)[0]), "r"((a)[1]), "r"((a)[2]), "r"((a)[3]), "r"(b0), "r"(b1))

// ============================================================
// Merged LN + prep kernel (unchanged)
// ============================================================
#define PREP_BLOCKS 2548

__global__ __launch_bounds__(256)
void ln_prep_kernel(const float* __restrict__ x, const float* __restrict__ norm_w,
                    const float* __restrict__ norm_b, __half* __restrict__ outh,
                    const float* __restrict__ wq, const float* __restrict__ wk,
                    const float* __restrict__ wr, const float* __restrict__ wv,
                    const float* __restrict__ bv, const float* __restrict__ br,
                    const float* __restrict__ gammap,
                    __half* __restrict__ wqkh, __half* __restrict__ wrh,
                    __half* __restrict__ wvth, float* __restrict__ bvr,
                    __half* __restrict__ semh, __half* __restrict__ kfh)
{
    __shared__ float tile[32][33];
    __shared__ float red[2][8];
    int bid = blockIdx.x;
    int t = threadIdx.x;

    if (bid >= PREP_BLOCKS) {
        int row = bid - PREP_BLOCKS;
        const float4* xr = (const float4*)(x + (size_t)row * CDIM);
        float4 v = xr[t];
        float s  = v.x + v.y + v.z + v.w;
        float sq = v.x*v.x + v.y*v.y + v.z*v.z + v.w*v.w;
        #pragma unroll
        for (int o = 16; o > 0; o >>= 1) {
            s  += __shfl_xor_sync(0xFFFFFFFFu, s,  o);
            sq += __shfl_xor_sync(0xFFFFFFFFu, sq, o);
        }
        int wid = t >> 5, lid = t & 31;
        if (lid == 0) { red[0][wid] = s; red[1][wid] = sq; }
        __syncthreads();
        float st = 0.f, sqt = 0.f;
        #pragma unroll
        for (int i = 0; i < 8; i++) { st += red[0][i]; sqt += red[1][i]; }
        float mu   = st * (1.0f / CDIM);
        float var  = sqt * (1.0f / CDIM) - mu * mu;
        float rstd = rsqrtf(var + 1e-5f);
        float4 wv4 = ((const float4*)norm_w)[t];
        float4 bv4 = ((const float4*)norm_b)[t];
        float4 o;
        o.x = (v.x - mu) * rstd * wv4.x + bv4.x;
        o.y = (v.y - mu) * rstd * wv4.y + bv4.y;
        o.z = (v.z - mu) * rstd * wv4.z + bv4.z;
        o.w = (v.w - mu) * rstd * wv4.w + bv4.w;
        __half2* hp = (__half2*)(outh + (size_t)row * CDIM + t * 4);
        hp[0] = __floats2half2_rn(o.x, o.y);
        hp[1] = __floats2half2_rn(o.z, o.w);
    } else if (bid < 300) {
        const float* in = (bid < 150) ? wq : wk;
        __half* out = wqkh + (bid < 150 ? 0 : (size_t)150 * CDIM);
        int i = (bid % 150) * 1024 + t * 4;
        float4 v = *(const float4*)(in + i);
        *(__half2*)(out + i)     = __floats2half2_rn(v.x, v.y);
        *(__half2*)(out + i + 2) = __floats2half2_rn(v.z, v.w);
    } else if (bid < 1324) {
        int i = (bid - 300) * 1024 + t * 4;
        float4 v = *(const float4*)(wr + i);
        *(__half2*)(wrh + i)     = __floats2half2_rn(v.x, v.y);
        *(__half2*)(wrh + i + 2) = __floats2half2_rn(v.z, v.w);
    } else if (bid < 2348) {
        int idx = bid - 1324;
        int bx = idx & 31, by = idx >> 5;
        int tx = t & 31, ty = t >> 5;
        int xx = bx * 32 + tx;
        int y0 = by * 32 + ty;
        #pragma unroll
        for (int i = 0; i < 32; i += 8)
            tile[ty + i][tx] = wv[(size_t)(y0 + i) * CDIM + xx];
        __syncthreads();
        int x2 = by * 32 + tx;
        int y2 = bx * 32 + ty;
        #pragma unroll
        for (int i = 0; i < 32; i += 8)
            wvth[(size_t)(y2 + i) * CDIM + x2] = __float2half_rn(tile[tx][ty + i]);
    } else if (bid < 2352) {
        int i = (bid - 2348) * 256 + t;
        const float4* w4 = (const float4*)(wr + (size_t)i * CDIM);
        const float4* b4 = (const float4*)bv;
        float s = 0.f;
        #pragma unroll 8
        for (int k = 0; k < 256; k++) {
            float4 a = w4[k], b = b4[k];
            s += a.x * b.x + a.y * b.y + a.z * b.z + a.w * b.w;
        }
        bvr[i] = gammap[0] * (s + br[i]);
    } else {
        int r = (bid - 2352) * 256 + t;
        if (r < M_ROWS) {
            __half2 z = __floats2half2_rn(0.f, 0.f);
            __half2* pa = (__half2*)(semh + (size_t)r * 160 + 150);
            __half2* pb = (__half2*)(kfh  + (size_t)r * 160 + 150);
            #pragma unroll
            for (int i = 0; i < 5; i++) { pa[i] = z; pb[i] = z; }
        }
    }
}

// ============================================================
// fp16 mma.sync GEMM (unchanged)
// ============================================================
template<int MODE, int BN, int WN>
__global__ __launch_bounds__(256, 1)
void gemm_h(const __half* __restrict__ A, const __half* __restrict__ W,
            const float* __restrict__ bias0, const float* __restrict__ bias1,
            float* __restrict__ C0, __half* __restrict__ H0, __half* __restrict__ H1,
            int Nvalid, int ldc,
            const __half* __restrict__ residh, const float* __restrict__ gammap)
{
    constexpr int S = 3;
    constexpr int A_BYTES = 128 * 128;
    constexpr int B_BYTES = BN * 128;
    constexpr int STAGE = A_BYTES + B_BYTES;
    constexpr int NITER = CDIM / 64;
    constexpr int BLD = BN / 32;
    constexpr int WM  = 8 / WN;
    constexpr int MT  = 128 / (WM * 16);
    constexpr int NT  = BN / (WN * 8);
    constexpr int NB2 = (NT + 1) / 2;

    extern __shared__ char smem_raw[];
    char* tiles = (char*)(((uintptr_t)smem_raw + 1023) & ~(uintptr_t)1023);
    const uint32_t base = smem_to_u32(tiles);

    const int tid = threadIdx.x;
    const int m0  = blockIdx.y * 128;
    const int n0  = blockIdx.x * BN;
    const int vrows = (Nvalid - n0 < BN) ? (Nvalid - n0) : BN;

    if (vrows < BN) {
        #pragma unroll
        for (int s = 0; s < S; s++) {
            float4* z = (float4*)(tiles + s * STAGE + A_BYTES + vrows * 128);
            int cnt = (BN - vrows) * 8;
            for (int i = tid; i < cnt; i += 256) z[i] = make_float4(0.f, 0.f, 0.f, 0.f);
        }
        __syncthreads();
    }

    auto load_stage = [&](int c) {
        int st = c % S;
        uint32_t as = base + st * STAGE;
        uint32_t bs = as + A_BYTES;
        const char* Ag = (const char*)A + (size_t)m0 * (CDIM * 2) + c * 128;
        const char* Wg = (const char*)W + (size_t)n0 * (CDIM * 2) + c * 128;
        #pragma unroll
        for (int i = 0; i < 4; i++) {
            int idx = tid + i * 256;
            int r = idx >> 3, u = idx & 7;
            CP_ASYNC16(as + r * 128 + ((u ^ (r & 7)) << 4),
                       Ag + (size_t)r * (CDIM * 2) + u * 16);
        }
        #pragma unroll
        for (int i = 0; i < BLD; i++) {
            int idx = tid + i * 256;
            int r = idx >> 3, u = idx & 7;
            if (r < vrows)
                CP_ASYNC16(bs + r * 128 + ((u ^ (r & 7)) << 4),
                           Wg + (size_t)r * (CDIM * 2) + u * 16);
        }
        CP_COMMIT();
    };

    load_stage(0);
    load_stage(1);

    float acc[MT][NT][4];
    #pragma unroll
    for (int i = 0; i < MT; i++)
        #pragma unroll
        for (int j = 0; j < NT; j++)
            #pragma unroll
            for (int q = 0; q < 4; q++) acc[i][j][q] = 0.f;

    const int lane = tid & 31;
    const int wid  = tid >> 5;
    const int wm = (wid & (WM - 1)) * (128 / WM);
    const int wn = (wid / WM) * (NT * 8);

    const int arow_l = wm + (lane & 15);
    const int au_l   = lane >> 4;
    const int brow_l = wn + (lane & 7) + ((lane >> 4) << 3);
    const int bu_l   = (lane >> 3) & 1;

    for (int it = 0; it < NITER; it++) {
        asm volatile("cp.async.wait_group 1;" ::: "memory");
        __syncthreads();
        if (it + 2 < NITER) load_stage(it + 2);

        uint32_t as = base + (it % S) * STAGE;
        uint32_t bs = as + A_BYTES;
        #pragma unroll
        for (int kk = 0; kk < 4; kk++) {
            uint32_t a[MT][4], b[NB2][4];
            #pragma unroll
            for (int mt = 0; mt < MT; mt++) {
                int row = arow_l + mt * 16;
                int u = kk * 2 + au_l;
                LDMATRIX_X4(a[mt][0], a[mt][1], a[mt][2], a[mt][3],
                            as + row * 128 + ((u ^ (row & 7)) << 4));
            }
            #pragma unroll
            for (int np = 0; np < NB2; np++) {
                int row = brow_l + np * 16;
                int u = kk * 2 + bu_l;
                LDMATRIX_X4(b[np][0], b[np][1], b[np][2], b[np][3],
                            bs + row * 128 + ((u ^ (row & 7)) << 4));
            }
            #pragma unroll
            for (int mt = 0; mt < MT; mt++)
                #pragma unroll
                for (int nt = 0; nt < NT; nt++)
                    MMA16816(acc[mt][nt], a[mt],
                             b[nt >> 1][(nt & 1) * 2], b[nt >> 1][(nt & 1) * 2 + 1]);
        }
    }

    const int g = lane >> 2, tig = lane & 3;
    #pragma unroll
    for (int mt = 0; mt < MT; mt++) {
        #pragma unroll
        for (int nt = 0; nt < NT; nt++) {
            int m = m0 + wm + mt * 16 + g;
            int n = n0 + wn + nt * 8 + tig * 2;
            if (MODE == 2) {
                if (n >= Nvalid) continue;
                #pragma unroll
                for (int h = 0; h < 2; h++) {
                    int mr = m + h * 8;
                    float v0, v1;
                    if (n < 150) {
                        v0 = acc[mt][nt][h*2+0] + bias0[n];
                        v1 = acc[mt][nt][h*2+1] + bias0[n + 1];
                        C0[(size_t)mr * 150 + n]     = v0;
                        C0[(size_t)mr * 150 + n + 1] = v1;
                        *(__half2*)(H0 + (size_t)mr * 160 + n) = __floats2half2_rn(v0, v1);
                    } else {
                        int nn = n - 150;
                        v0 = acc[mt][nt][h*2+0] + bias1[nn];
                        v1 = acc[mt][nt][h*2+1] + bias1[nn + 1];
                        *(__half2*)(H1 + (size_t)mr * 160 + nn) = __floats2half2_rn(v0, v1);
                    }
                }
            } else if (MODE == 4) {
                float gm = gammap[0];
                #pragma unroll
                for (int h = 0; h < 2; h++) {
                    int mr = m + h * 8;
                    *(__half2*)(H0 + (size_t)mr * ldc + n) =
                        __floats2half2_rn(gm * acc[mt][nt][h*2+0], gm * acc[mt][nt][h*2+1]);
                }
            } else { // MODE 1
                float b0 = bias0[n], b1 = bias0[n + 1];
                #pragma unroll
                for (int h = 0; h < 2; h++) {
                    int mr = m + h * 8;
                    __half2 rv = *(const __half2*)(residh + (size_t)mr * CDIM + n);
                    float v0 = acc[mt][nt][h*2+0] + b0 + __low2float(rv);
                    float v1 = acc[mt][nt][h*2+1] + b1 + __high2float(rv);
                    *(float2*)(C0 + (size_t)mr * ldc + n) = make_float2(v0, v1);
                }
            }
        }
    }
}

// ============================================================
// HMMA attention: 2 windows per block, register softmax,
// cross-window QK prefetch, double-buffered V, hoisted S frags,
// precomputed per-window row-index table (kills div/mod in hot loops).
// ============================================================
#define QK_STRB 336
#define SH_STRB 144
#define VC_STRB 272
#define SH_OFF  43008
#define V_OFF   52224
#define V_BUFB  17408
#define ATTN_SMEM (52224 + 2 * 17408)  // 87040

__global__ __launch_bounds__(128)
void attn_mma(const __half* __restrict__ semh, const __half* __restrict__ kfh,
              const __half* __restrict__ vh, __half* __restrict__ ao)
{
    extern __shared__ char sm[];
    char* Qc  = sm;
    char* Kc  = sm + 21504;
    char* Shc = sm + SH_OFF;
    char* Vb0 = sm + V_OFF;
    __shared__ int s_row[2][49];   // global row index per window token

    const uint32_t qb  = smem_to_u32(Qc);
    const uint32_t kb  = smem_to_u32(Kc);
    const uint32_t shb = smem_to_u32(Shc);
    const uint32_t vbb = smem_to_u32(Vb0);

    int t = threadIdx.x;
    const int lane = t & 31, w = t >> 5;
    const int g = lane >> 2, tig = lane & 3;
    const int wi0 = blockIdx.x * 2;

    // ---- fill row tables + pad zeroing, one barrier
    if (t < 98) {
        int wl = t >= 49;
        int m  = t - wl * 49;
        int wi = wi0 + wl;
        int b  = wi >> 6;
        int wh = (wi >> 3) & 7;
        int ww = wi & 7;
        s_row[wl][m] = b * BATCH_STRIDE + wh * 7 * 56 + ww * 7 + (m / 7) * 56 + (m % 7);
    }
    for (int i = t; i < 630; i += 128) {
        char* buf = (i < 315) ? Qc : Kc;
        int idx = (i < 315) ? i : i - 315;
        int row = 49 + idx / 21, u = idx % 21;
        ((float4*)(buf + row * QK_STRB))[u] = make_float4(0.f, 0.f, 0.f, 0.f);
    }
    for (int i = t; i < 510; i += 128) {
        int bsel = i >= 255;
        int idx = i - bsel * 255;
        int row = 49 + idx / 17, u = idx % 17;
        ((float4*)(Vb0 + bsel * V_BUFB + row * VC_STRB))[u] = make_float4(0.f, 0.f, 0.f, 0.f);
    }
    __syncthreads();

    auto issue_qk = [&](int wl) {
        for (int idx = t; idx < 1960; idx += 128) {
            int which = idx >= 980;
            int i2 = idx - which * 980;
            int n = i2 / 20, u = i2 % 20;
            int r = s_row[wl][n];
            uint32_t dst = (which ? kb : qb) + n * QK_STRB + u * 16;
            const char* src = (const char*)(which ? kfh : semh) + (size_t)r * 320 + u * 16;
            CP_ASYNC16(dst, src);
        }
        CP_COMMIT();
    };
    auto issue_v = [&](int wl, int cc) {
        uint32_t nb = vbb + (cc & 1) * V_BUFB;
        for (int idx = t; idx < 49 * 16; idx += 128) {
            int m = idx >> 4, u = idx & 15;
            int r = s_row[wl][m];
            CP_ASYNC16(nb + m * VC_STRB + u * 16,
                       (const char*)vh + (size_t)r * 2048 + cc * 256 + u * 16);
        }
        CP_COMMIT();
    };

    issue_qk(0);

    for (int wl = 0; wl < 2; wl++) {
        issue_v(wl, 0);
        if (wl == 0) {
            asm volatile("cp.async.wait_group 0;" ::: "memory");
        }
        __syncthreads();

        // ---- Phase A: S = Q K^T
        float accS[8][4];
        #pragma unroll
        for (int j = 0; j < 8; j++)
            #pragma unroll
            for (int q = 0; q < 4; q++) accS[j][q] = 0.f;
        {
            const int arow = 16 * w + (lane & 15);
            const int ak   = (lane >> 4) * 8;
            const int brow = (lane & 7) + ((lane >> 4) << 3);
            const int bk   = ((lane >> 3) & 1) * 8;
            #pragma unroll
            for (int ks = 0; ks < 10; ks++) {
                uint32_t a[4], bfr[4][4];
                LDMATRIX_X4(a[0], a[1], a[2], a[3],
                            qb + arow * QK_STRB + (ks * 16 + ak) * 2);
                #pragma unroll
                for (int np = 0; np < 4; np++)
                    LDMATRIX_X4(bfr[np][0], bfr[np][1], bfr[np][2], bfr[np][3],
                                kb + (brow + np * 16) * QK_STRB + (ks * 16 + bk) * 2);
                #pragma unroll
                for (int nt = 0; nt < 8; nt++)
                    MMA16816(accS[nt], a, bfr[nt >> 1][(nt & 1) * 2], bfr[nt >> 1][(nt & 1) * 2 + 1]);
            }
        }

        // ---- register softmax (quad shfl) + write half S to Shc
        {
            int r0 = 16 * w + g;
            float m0 = -1e30f, m1 = -1e30f;
            #pragma unroll
            for (int nt = 0; nt < 8; nt++)
                #pragma unroll
                for (int e = 0; e < 2; e++) {
                    int c = nt * 8 + tig * 2 + e;
                    if (c < 49) {
                        m0 = fmaxf(m0, accS[nt][e]);
                        m1 = fmaxf(m1, accS[nt][2 + e]);
                    }
                }
            m0 = fmaxf(m0, __shfl_xor_sync(0xFFFFFFFFu, m0, 1));
            m0 = fmaxf(m0, __shfl_xor_sync(0xFFFFFFFFu, m0, 2));
            m1 = fmaxf(m1, __shfl_xor_sync(0xFFFFFFFFu, m1, 1));
            m1 = fmaxf(m1, __shfl_xor_sync(0xFFFFFFFFu, m1, 2));
            float s0 = 0.f, s1 = 0.f;
            #pragma unroll
            for (int nt = 0; nt < 8; nt++)
                #pragma unroll
                for (int e = 0; e < 2; e++) {
                    int c = nt * 8 + tig * 2 + e;
                    float e0 = 0.f, e1 = 0.f;
                    if (c < 49) {
                        e0 = __expf(accS[nt][e]     - m0);
                        e1 = __expf(accS[nt][2 + e] - m1);
                    }
                    accS[nt][e] = e0;     s0 += e0;
                    accS[nt][2 + e] = e1; s1 += e1;
                }
            s0 += __shfl_xor_sync(0xFFFFFFFFu, s0, 1);
            s0 += __shfl_xor_sync(0xFFFFFFFFu, s0, 2);
            s1 += __shfl_xor_sync(0xFFFFFFFFu, s1, 1);
            s1 += __shfl_xor_sync(0xFFFFFFFFu, s1, 2);
            float inv0 = 1.f / s0, inv1 = 1.f / s1;
            __half2* d0 = (__half2*)(Shc + r0 * SH_STRB + tig * 4);
            __half2* d1 = (__half2*)(Shc + (r0 + 8) * SH_STRB + tig * 4);
            #pragma unroll
            for (int nt = 0; nt < 8; nt++) {
                __half2 h0 = (r0 < 49)
                    ? __floats2half2_rn(accS[nt][0] * inv0, accS[nt][1] * inv0)
                    : __floats2half2_rn(0.f, 0.f);
                __half2 h1 = (r0 + 8 < 49)
                    ? __floats2half2_rn(accS[nt][2] * inv1, accS[nt][3] * inv1)
                    : __floats2half2_rn(0.f, 0.f);
                d0[nt * 4] = h0;
                d1[nt * 4] = h1;
            }
        }
        __syncthreads();  // Shc visible; Qc/Kc free for prefetch

        // ---- hoist S fragments into registers (reused by all 8 chunks)
        const int arow = lane & 15;
        const int ak   = (lane >> 4) * 8;
        uint32_t sA[4][4][4];
        #pragma unroll
        for (int ks = 0; ks < 4; ks++)
            #pragma unroll
            for (int mt = 0; mt < 4; mt++)
                LDMATRIX_X4(sA[ks][mt][0], sA[ks][mt][1], sA[ks][mt][2], sA[ks][mt][3],
                            shb + (16 * mt + arow) * SH_STRB + (ks * 16 + ak) * 2);

        // ---- Phase B: O = S V, double-buffered; prefetch next QK at cc==0
        const int kk_l = (lane & 7) + ((lane >> 3) & 1) * 8;
        const int nc_l = 32 * w + ((lane >> 4) << 3);

        for (int cc = 0; cc < 8; cc++) {
            if (cc + 1 < 8) {
                issue_v(wl, cc + 1);
                if (cc == 0 && wl == 0) issue_qk(1);
                asm volatile("cp.async.wait_group 1;" ::: "memory");
            } else {
                asm volatile("cp.async.wait_group 0;" ::: "memory");
            }
            __syncthreads();

            const uint32_t vb = vbb + (cc & 1) * V_BUFB;
            float acc[4][4][4];
            #pragma unroll
            for (int i = 0; i < 4; i++)
                #pragma unroll
                for (int j = 0; j < 4; j++)
                    #pragma unroll
                    for (int q = 0; q < 4; q++) acc[i][j][q] = 0.f;

            #pragma unroll
            for (int ks = 0; ks < 4; ks++) {
                uint32_t bq[2][4];
                #pragma unroll
                for (int nb2 = 0; nb2 < 2; nb2++)
                    LDMATRIX_X4_T(bq[nb2][0], bq[nb2][1], bq[nb2][2], bq[nb2][3],
                                  vb + (ks * 16 + kk_l) * VC_STRB + (nc_l + nb2 * 16) * 2);
                #pragma unroll
                for (int mt = 0; mt < 4; mt++)
                    #pragma unroll
                    for (int nt = 0; nt < 4; nt++)
                        MMA16816(acc[mt][nt], sA[ks][mt],
                                 bq[nt >> 1][(nt & 1) * 2], bq[nt >> 1][(nt & 1) * 2 + 1]);
            }

            #pragma unroll
            for (int mt = 0; mt < 4; mt++) {
                #pragma unroll
                for (int h = 0; h < 2; h++) {
                    int m = 16 * mt + g + h * 8;
                    if (m < 49) {
                        int r = s_row[wl][m];
                        __half* dst = ao + (size_t)r * CDIM + cc * 128;
                        #pragma unroll
                        for (int nt = 0; nt < 4; nt++) {
                            int n = 32 * w + nt * 8 + tig * 2;
                            *(__half2*)(dst + n) =
                                __floats2half2_rn(acc[mt][nt][h*2+0], acc[mt][nt][h*2+1]);
                        }
                    }
                }
            }
            if (cc < 7) __syncthreads();  // next chunk overwrites the other V buffer
        }
        // no trailing barrier: next window's first V write targets buffer 0,
        // disjoint from buffer 1 still being read; window-start barrier covers the rest
    }
}

// ============================================================
// Host launcher
// ============================================================
extern "C" void kernel_launch(void* const* d_in, const int* in_sizes, int n_in,
                              void* d_out, int out_size)
{
    const float* x      = (const float*)d_in[0];
    const float* norm_w = (const float*)d_in[1];
    const float* norm_b = (const float*)d_in[2];
    const float* wq     = (const float*)d_in[3];
    const float* bq     = (const float*)d_in[4];
    const float* wk     = (const float*)d_in[5];
    const float* bk     = (const float*)d_in[6];
    const float* wv     = (const float*)d_in[7];
    const float* bv     = (const float*)d_in[8];
    const float* wr     = (const float*)d_in[9];
    const float* br     = (const float*)d_in[10];
    const float* gamma  = (const float*)d_in[11];
    (void)in_sizes; (void)n_in; (void)out_size;

    float* out  = (float*)d_out;
    float* sem  = out;
    float* xout = out + (size_t)M_ROWS * KSEM;

    __half *xnh, *semh, *kfh, *aoh, *wqkh, *wrh, *wvth, *wch;
    float* bvr;
    cudaGetSymbolAddress((void**)&xnh,  g_xnh);
    cudaGetSymbolAddress((void**)&semh, g_semh);
    cudaGetSymbolAddress((void**)&kfh,  g_kfh);
    cudaGetSymbolAddress((void**)&aoh,  g_aoh);
    cudaGetSymbolAddress((void**)&wqkh, g_wqkh);
    cudaGetSymbolAddress((void**)&wrh,  g_wrh);
    cudaGetSymbolAddress((void**)&wvth, g_wvth);
    cudaGetSymbolAddress((void**)&wch,  g_wch);
    cudaGetSymbolAddress((void**)&bvr,  g_bvr);

    const int SMEM256 = 3 * 49152 + 1024;
    const int SMEM160 = 3 * 36864 + 1024;
    const int SMEM128 = 3 * 32768 + 1024;
    cudaFuncSetAttribute(gemm_h<1, 256, 4>, cudaFuncAttributeMaxDynamicSharedMemorySize, SMEM256);
    cudaFuncSetAttribute(gemm_h<2, 160, 2>, cudaFuncAttributeMaxDynamicSharedMemorySize, SMEM160);
    cudaFuncSetAttribute(gemm_h<4, 128, 2>, cudaFuncAttributeMaxDynamicSharedMemorySize, SMEM128);
    cudaFuncSetAttribute(attn_mma, cudaFuncAttributeMaxDynamicSharedMemorySize, ATTN_SMEM);

    // 0+1) merged prep + LayerNorm
    ln_prep_kernel<<<PREP_BLOCKS + M_ROWS, 256>>>(x, norm_w, norm_b, xnh,
                                                  wq, wk, wr, wv, bv, br, gamma,
                                                  wqkh, wrh, wvth, bvr, semh, kfh);

    // Wc = gamma * Wr @ Wv (half)
    gemm_h<4, 128, 2><<<dim3(8, 8), 256, SMEM128>>>(wrh, wvth, nullptr, nullptr,
                                                    nullptr, wch, nullptr, CDIM, CDIM, nullptr, gamma);

    // 2) merged Q/K projection
    gemm_h<2, 160, 2><<<dim3(2, M_ROWS / 128), 256, SMEM160>>>(xnh, wqkh, bq, bk, sem, semh, kfh,
                                                               300, KSEM, nullptr, nullptr);

    // 3) attention: 2 windows per block
    attn_mma<<<NWIN / 2, 128, ATTN_SMEM>>>(semh, kfh, xnh, aoh);

    // 4) xout = aoh @ Wc^T + bvr + xnh
    gemm_h<1, 256, 4><<<dim3(4, M_ROWS / 128), 256, SMEM256>>>(aoh, wch, bvr, nullptr, xout,
                                                               nullptr, nullptr, CDIM, CDIM, xnh, nullptr);
}

// round 14
// speedup vs baseline: 1.0028x; 1.0028x over previous
#include <cuda_runtime.h>
#include <cuda_fp16.h>
#include <cstdint>
#include <cstddef>

// Problem constants (B=16, H=W=56, C=1024, K=150, WS=7)
#define M_ROWS 50176
#define CDIM   1024
#define KSEM   150
#define NWIN   1024
#define BATCH_STRIDE 3136

// -------- scratch (device globals) --------
__device__ __half g_xnh [(size_t)M_ROWS * CDIM];   // LN out half
__device__ __half g_semh[(size_t)M_ROWS * 160];    // seg_map half, padded stride
__device__ __half g_kfh [(size_t)M_ROWS * 160];    // seg_ft half, padded stride
__device__ __half g_aoh [(size_t)M_ROWS * CDIM];   // attention out half
__device__ __half g_wqkh[(size_t)300 * CDIM];      // wq(150) + wk(150) stacked
__device__ __half g_wrh [(size_t)CDIM * CDIM];     // wr half
__device__ __half g_wvth[(size_t)CDIM * CDIM];     // wv^T half
__device__ __half g_wch [(size_t)CDIM * CDIM];     // Wc = gamma * Wr @ Wv, half
__device__ float  g_bvr [CDIM];                    // gamma * (Wr @ bv + br)

__device__ __forceinline__ uint32_t smem_to_u32(const void* p) {
    uint32_t a;
    asm("{ .reg .u64 t; cvta.to.shared.u64 t, %1; cvt.u32.u64 %0, t; }" : "=r"(a) : "l"(p));
    return a;
}
#define CP_ASYNC16(dst, src) \
    asm volatile("cp.async.cg.shared.global [%0], [%1], 16;" :: "r"(dst), "l"(src) : "memory")
#define CP_COMMIT() asm volatile("cp.async.commit_group;" ::: "memory")
#define LDMATRIX_X4(r0, r1, r2, r3, addr) \
    asm volatile("ldmatrix.sync.aligned.m8n8.x4.shared.b16 {%0,%1,%2,%3}, [%4];" \
        : "=r"(r0), "=r"(r1), "=r"(r2), "=r"(r3) : "r"(addr))
#define LDMATRIX_X4_T(r0, r1, r2, r3, addr) \
    asm volatile("ldmatrix.sync.aligned.m8n8.x4.trans.shared.b16 {%0,%1,%2,%3}, [%4];" \
        : "=r"(r0), "=r"(r1), "=r"(r2), "=r"(r3) : "r"(addr))
#define MMA16816(acc, a, b0, b1) \
    asm volatile("mma.sync.aligned.m16n8k16.row.col.f32.f16.f16.f32 " \
        "{%0,%1,%2,%3}, {%4,%5,%6,%7}, {%8,%9}, {%0,%1,%2,%3};" \
        : "+f"((acc)[0]), "+f"((acc)[1]), "+f"((acc)[2]), "+f"((acc)[3]) \
        : "r"((a)[0]), "r"((a)[1]), "r"((a)[2]), "r"((a)[3]), "r"(b0), "r"(b1))

// ============================================================
// Merged LN + prep kernel (unchanged)
// ============================================================
#define PREP_BLOCKS 2548

__global__ __launch_bounds__(256)
void ln_prep_kernel(const float* __restrict__ x, const float* __restrict__ norm_w,
                    const float* __restrict__ norm_b, __half* __restrict__ outh,
                    const float* __restrict__ wq, const float* __restrict__ wk,
                    const float* __restrict__ wr, const float* __restrict__ wv,
                    const float* __restrict__ bv, const float* __restrict__ br,
                    const float* __restrict__ gammap,
                    __half* __restrict__ wqkh, __half* __restrict__ wrh,
                    __half* __restrict__ wvth, float* __restrict__ bvr,
                    __half* __restrict__ semh, __half* __restrict__ kfh)
{
    __shared__ float tile[32][33];
    __shared__ float red[2][8];
    int bid = blockIdx.x;
    int t = threadIdx.x;

    if (bid >= PREP_BLOCKS) {
        int row = bid - PREP_BLOCKS;
        const float4* xr = (const float4*)(x + (size_t)row * CDIM);
        float4 v = xr[t];
        float s  = v.x + v.y + v.z + v.w;
        float sq = v.x*v.x + v.y*v.y + v.z*v.z + v.w*v.w;
        #pragma unroll
        for (int o = 16; o > 0; o >>= 1) {
            s  += __shfl_xor_sync(0xFFFFFFFFu, s,  o);
            sq += __shfl_xor_sync(0xFFFFFFFFu, sq, o);
        }
        int wid = t >> 5, lid = t & 31;
        if (lid == 0) { red[0][wid] = s; red[1][wid] = sq; }
        __syncthreads();
        float st = 0.f, sqt = 0.f;
        #pragma unroll
        for (int i = 0; i < 8; i++) { st += red[0][i]; sqt += red[1][i]; }
        float mu   = st * (1.0f / CDIM);
        float var  = sqt * (1.0f / CDIM) - mu * mu;
        float rstd = rsqrtf(var + 1e-5f);
        float4 wv4 = ((const float4*)norm_w)[t];
        float4 bv4 = ((const float4*)norm_b)[t];
        float4 o;
        o.x = (v.x - mu) * rstd * wv4.x + bv4.x;
        o.y = (v.y - mu) * rstd * wv4.y + bv4.y;
        o.z = (v.z - mu) * rstd * wv4.z + bv4.z;
        o.w = (v.w - mu) * rstd * wv4.w + bv4.w;
        __half2* hp = (__half2*)(outh + (size_t)row * CDIM + t * 4);
        hp[0] = __floats2half2_rn(o.x, o.y);
        hp[1] = __floats2half2_rn(o.z, o.w);
    } else if (bid < 300) {
        const float* in = (bid < 150) ? wq : wk;
        __half* out = wqkh + (bid < 150 ? 0 : (size_t)150 * CDIM);
        int i = (bid % 150) * 1024 + t * 4;
        float4 v = *(const float4*)(in + i);
        *(__half2*)(out + i)     = __floats2half2_rn(v.x, v.y);
        *(__half2*)(out + i + 2) = __floats2half2_rn(v.z, v.w);
    } else if (bid < 1324) {
        int i = (bid - 300) * 1024 + t * 4;
        float4 v = *(const float4*)(wr + i);
        *(__half2*)(wrh + i)     = __floats2half2_rn(v.x, v.y);
        *(__half2*)(wrh + i + 2) = __floats2half2_rn(v.z, v.w);
    } else if (bid < 2348) {
        int idx = bid - 1324;
        int bx = idx & 31, by = idx >> 5;
        int tx = t & 31, ty = t >> 5;
        int xx = bx * 32 + tx;
        int y0 = by * 32 + ty;
        #pragma unroll
        for (int i = 0; i < 32; i += 8)
            tile[ty + i][tx] = wv[(size_t)(y0 + i) * CDIM + xx];
        __syncthreads();
        int x2 = by * 32 + tx;
        int y2 = bx * 32 + ty;
        #pragma unroll
        for (int i = 0; i < 32; i += 8)
            wvth[(size_t)(y2 + i) * CDIM + x2] = __float2half_rn(tile[tx][ty + i]);
    } else if (bid < 2352) {
        int i = (bid - 2348) * 256 + t;
        const float4* w4 = (const float4*)(wr + (size_t)i * CDIM);
        const float4* b4 = (const float4*)bv;
        float s = 0.f;
        #pragma unroll 8
        for (int k = 0; k < 256; k++) {
            float4 a = w4[k], b = b4[k];
            s += a.x * b.x + a.y * b.y + a.z * b.z + a.w * b.w;
        }
        bvr[i] = gammap[0] * (s + br[i]);
    } else {
        int r = (bid - 2352) * 256 + t;
        if (r < M_ROWS) {
            __half2 z = __floats2half2_rn(0.f, 0.f);
            __half2* pa = (__half2*)(semh + (size_t)r * 160 + 150);
            __half2* pb = (__half2*)(kfh  + (size_t)r * 160 + 150);
            #pragma unroll
            for (int i = 0; i < 5; i++) { pa[i] = z; pb[i] = z; }
        }
    }
}

// ============================================================
// fp16 mma.sync GEMM (unchanged)
// ============================================================
template<int MODE, int BN, int WN>
__global__ __launch_bounds__(256, 1)
void gemm_h(const __half* __restrict__ A, const __half* __restrict__ W,
            const float* __restrict__ bias0, const float* __restrict__ bias1,
            float* __restrict__ C0, __half* __restrict__ H0, __half* __restrict__ H1,
            int Nvalid, int ldc,
            const __half* __restrict__ residh, const float* __restrict__ gammap)
{
    constexpr int S = 3;
    constexpr int A_BYTES = 128 * 128;
    constexpr int B_BYTES = BN * 128;
    constexpr int STAGE = A_BYTES + B_BYTES;
    constexpr int NITER = CDIM / 64;
    constexpr int BLD = BN / 32;
    constexpr int WM  = 8 / WN;
    constexpr int MT  = 128 / (WM * 16);
    constexpr int NT  = BN / (WN * 8);
    constexpr int NB2 = (NT + 1) / 2;

    extern __shared__ char smem_raw[];
    char* tiles = (char*)(((uintptr_t)smem_raw + 1023) & ~(uintptr_t)1023);
    const uint32_t base = smem_to_u32(tiles);

    const int tid = threadIdx.x;
    const int m0  = blockIdx.y * 128;
    const int n0  = blockIdx.x * BN;
    const int vrows = (Nvalid - n0 < BN) ? (Nvalid - n0) : BN;

    if (vrows < BN) {
        #pragma unroll
        for (int s = 0; s < S; s++) {
            float4* z = (float4*)(tiles + s * STAGE + A_BYTES + vrows * 128);
            int cnt = (BN - vrows) * 8;
            for (int i = tid; i < cnt; i += 256) z[i] = make_float4(0.f, 0.f, 0.f, 0.f);
        }
        __syncthreads();
    }

    auto load_stage = [&](int c) {
        int st = c % S;
        uint32_t as = base + st * STAGE;
        uint32_t bs = as + A_BYTES;
        const char* Ag = (const char*)A + (size_t)m0 * (CDIM * 2) + c * 128;
        const char* Wg = (const char*)W + (size_t)n0 * (CDIM * 2) + c * 128;
        #pragma unroll
        for (int i = 0; i < 4; i++) {
            int idx = tid + i * 256;
            int r = idx >> 3, u = idx & 7;
            CP_ASYNC16(as + r * 128 + ((u ^ (r & 7)) << 4),
                       Ag + (size_t)r * (CDIM * 2) + u * 16);
        }
        #pragma unroll
        for (int i = 0; i < BLD; i++) {
            int idx = tid + i * 256;
            int r = idx >> 3, u = idx & 7;
            if (r < vrows)
                CP_ASYNC16(bs + r * 128 + ((u ^ (r & 7)) << 4),
                           Wg + (size_t)r * (CDIM * 2) + u * 16);
        }
        CP_COMMIT();
    };

    load_stage(0);
    load_stage(1);

    float acc[MT][NT][4];
    #pragma unroll
    for (int i = 0; i < MT; i++)
        #pragma unroll
        for (int j = 0; j < NT; j++)
            #pragma unroll
            for (int q = 0; q < 4; q++) acc[i][j][q] = 0.f;

    const int lane = tid & 31;
    const int wid  = tid >> 5;
    const int wm = (wid & (WM - 1)) * (128 / WM);
    const int wn = (wid / WM) * (NT * 8);

    const int arow_l = wm + (lane & 15);
    const int au_l   = lane >> 4;
    const int brow_l = wn + (lane & 7) + ((lane >> 4) << 3);
    const int bu_l   = (lane >> 3) & 1;

    for (int it = 0; it < NITER; it++) {
        asm volatile("cp.async.wait_group 1;" ::: "memory");
        __syncthreads();
        if (it + 2 < NITER) load_stage(it + 2);

        uint32_t as = base + (it % S) * STAGE;
        uint32_t bs = as + A_BYTES;
        #pragma unroll
        for (int kk = 0; kk < 4; kk++) {
            uint32_t a[MT][4], b[NB2][4];
            #pragma unroll
            for (int mt = 0; mt < MT; mt++) {
                int row = arow_l + mt * 16;
                int u = kk * 2 + au_l;
                LDMATRIX_X4(a[mt][0], a[mt][1], a[mt][2], a[mt][3],
                            as + row * 128 + ((u ^ (row & 7)) << 4));
            }
            #pragma unroll
            for (int np = 0; np < NB2; np++) {
                int row = brow_l + np * 16;
                int u = kk * 2 + bu_l;
                LDMATRIX_X4(b[np][0], b[np][1], b[np][2], b[np][3],
                            bs + row * 128 + ((u ^ (row & 7)) << 4));
            }
            #pragma unroll
            for (int mt = 0; mt < MT; mt++)
                #pragma unroll
                for (int nt = 0; nt < NT; nt++)
                    MMA16816(acc[mt][nt], a[mt],
                             b[nt >> 1][(nt & 1) * 2], b[nt >> 1][(nt & 1) * 2 + 1]);
        }
    }

    const int g = lane >> 2, tig = lane & 3;
    #pragma unroll
    for (int mt = 0; mt < MT; mt++) {
        #pragma unroll
        for (int nt = 0; nt < NT; nt++) {
            int m = m0 + wm + mt * 16 + g;
            int n = n0 + wn + nt * 8 + tig * 2;
            if (MODE == 2) {
                if (n >= Nvalid) continue;
                #pragma unroll
                for (int h = 0; h < 2; h++) {
                    int mr = m + h * 8;
                    float v0, v1;
                    if (n < 150) {
                        v0 = acc[mt][nt][h*2+0] + bias0[n];
                        v1 = acc[mt][nt][h*2+1] + bias0[n + 1];
                        C0[(size_t)mr * 150 + n]     = v0;
                        C0[(size_t)mr * 150 + n + 1] = v1;
                        *(__half2*)(H0 + (size_t)mr * 160 + n) = __floats2half2_rn(v0, v1);
                    } else {
                        int nn = n - 150;
                        v0 = acc[mt][nt][h*2+0] + bias1[nn];
                        v1 = acc[mt][nt][h*2+1] + bias1[nn + 1];
                        *(__half2*)(H1 + (size_t)mr * 160 + nn) = __floats2half2_rn(v0, v1);
                    }
                }
            } else if (MODE == 4) {
                float gm = gammap[0];
                #pragma unroll
                for (int h = 0; h < 2; h++) {
                    int mr = m + h * 8;
                    *(__half2*)(H0 + (size_t)mr * ldc + n) =
                        __floats2half2_rn(gm * acc[mt][nt][h*2+0], gm * acc[mt][nt][h*2+1]);
                }
            } else { // MODE 1
                float b0 = bias0[n], b1 = bias0[n + 1];
                #pragma unroll
                for (int h = 0; h < 2; h++) {
                    int mr = m + h * 8;
                    __half2 rv = *(const __half2*)(residh + (size_t)mr * CDIM + n);
                    float v0 = acc[mt][nt][h*2+0] + b0 + __low2float(rv);
                    float v1 = acc[mt][nt][h*2+1] + b1 + __high2float(rv);
                    *(float2*)(C0 + (size_t)mr * ldc + n) = make_float2(v0, v1);
                }
            }
        }
    }
}

// ============================================================
// HMMA attention (R12 structure: inline div/mod addressing,
// hoisted S fragments) + trailing-barrier trim only.
// ============================================================
#define QK_STRB 336
#define SH_STRB 144
#define VC_STRB 272
#define SH_OFF  43008
#define V_OFF   52224
#define V_BUFB  17408
#define ATTN_SMEM (52224 + 2 * 17408)  // 87040

__global__ __launch_bounds__(128)
void attn_mma(const __half* __restrict__ semh, const __half* __restrict__ kfh,
              const __half* __restrict__ vh, __half* __restrict__ ao)
{
    extern __shared__ char sm[];
    char* Qc  = sm;
    char* Kc  = sm + 21504;
    char* Shc = sm + SH_OFF;
    char* Vb0 = sm + V_OFF;

    const uint32_t qb  = smem_to_u32(Qc);
    const uint32_t kb  = smem_to_u32(Kc);
    const uint32_t shb = smem_to_u32(Shc);
    const uint32_t vbb = smem_to_u32(Vb0);

    int t = threadIdx.x;
    const int lane = t & 31, w = t >> 5;
    const int g = lane >> 2, tig = lane & 3;

    auto win_base = [](int wi) {
        int b  = wi >> 6;
        int wh = (wi >> 3) & 7;
        int ww = wi & 7;
        return b * BATCH_STRIDE + wh * 7 * 56 + ww * 7;
    };
    auto issue_qk = [&](int base) {
        for (int idx = t; idx < 1960; idx += 128) {
            int which = idx >= 980;
            int i2 = idx - which * 980;
            int n = i2 / 20, u = i2 % 20;
            int r = base + (n / 7) * 56 + (n % 7);
            uint32_t dst = (which ? kb : qb) + n * QK_STRB + u * 16;
            const char* src = (const char*)(which ? kfh : semh) + (size_t)r * 320 + u * 16;
            CP_ASYNC16(dst, src);
        }
        CP_COMMIT();
    };
    auto issue_v = [&](int base, int cc) {
        uint32_t nb = vbb + (cc & 1) * V_BUFB;
        for (int idx = t; idx < 49 * 16; idx += 128) {
            int m = idx >> 4, u = idx & 15;
            int r = base + (m / 7) * 56 + (m % 7);
            CP_ASYNC16(nb + m * VC_STRB + u * 16,
                       (const char*)vh + (size_t)r * 2048 + cc * 256 + u * 16);
        }
        CP_COMMIT();
    };

    // ---- one-time pad zeroing (rows 49..63 of Qc/Kc and both V buffers)
    for (int i = t; i < 630; i += 128) {
        char* buf = (i < 315) ? Qc : Kc;
        int idx = (i < 315) ? i : i - 315;
        int row = 49 + idx / 21, u = idx % 21;
        ((float4*)(buf + row * QK_STRB))[u] = make_float4(0.f, 0.f, 0.f, 0.f);
    }
    for (int i = t; i < 510; i += 128) {
        int bsel = i >= 255;
        int idx = i - bsel * 255;
        int row = 49 + idx / 17, u = idx % 17;
        ((float4*)(Vb0 + bsel * V_BUFB + row * VC_STRB))[u] = make_float4(0.f, 0.f, 0.f, 0.f);
    }

    const int wi0 = blockIdx.x * 2;
    issue_qk(win_base(wi0));

    for (int wl = 0; wl < 2; wl++) {
        const int base = win_base(wi0 + wl);
        issue_v(base, 0);
        if (wl == 0) {
            asm volatile("cp.async.wait_group 0;" ::: "memory");
        }
        __syncthreads();

        // ---- Phase A: S = Q K^T
        float accS[8][4];
        #pragma unroll
        for (int j = 0; j < 8; j++)
            #pragma unroll
            for (int q = 0; q < 4; q++) accS[j][q] = 0.f;
        {
            const int arow = 16 * w + (lane & 15);
            const int ak   = (lane >> 4) * 8;
            const int brow = (lane & 7) + ((lane >> 4) << 3);
            const int bk   = ((lane >> 3) & 1) * 8;
            #pragma unroll
            for (int ks = 0; ks < 10; ks++) {
                uint32_t a[4], bfr[4][4];
                LDMATRIX_X4(a[0], a[1], a[2], a[3],
                            qb + arow * QK_STRB + (ks * 16 + ak) * 2);
                #pragma unroll
                for (int np = 0; np < 4; np++)
                    LDMATRIX_X4(bfr[np][0], bfr[np][1], bfr[np][2], bfr[np][3],
                                kb + (brow + np * 16) * QK_STRB + (ks * 16 + bk) * 2);
                #pragma unroll
                for (int nt = 0; nt < 8; nt++)
                    MMA16816(accS[nt], a, bfr[nt >> 1][(nt & 1) * 2], bfr[nt >> 1][(nt & 1) * 2 + 1]);
            }
        }

        // ---- register softmax (quad shfl) + write half S to Shc
        {
            int r0 = 16 * w + g;
            float m0 = -1e30f, m1 = -1e30f;
            #pragma unroll
            for (int nt = 0; nt < 8; nt++)
                #pragma unroll
                for (int e = 0; e < 2; e++) {
                    int c = nt * 8 + tig * 2 + e;
                    if (c < 49) {
                        m0 = fmaxf(m0, accS[nt][e]);
                        m1 = fmaxf(m1, accS[nt][2 + e]);
                    }
                }
            m0 = fmaxf(m0, __shfl_xor_sync(0xFFFFFFFFu, m0, 1));
            m0 = fmaxf(m0, __shfl_xor_sync(0xFFFFFFFFu, m0, 2));
            m1 = fmaxf(m1, __shfl_xor_sync(0xFFFFFFFFu, m1, 1));
            m1 = fmaxf(m1, __shfl_xor_sync(0xFFFFFFFFu, m1, 2));
            float s0 = 0.f, s1 = 0.f;
            #pragma unroll
            for (int nt = 0; nt < 8; nt++)
                #pragma unroll
                for (int e = 0; e < 2; e++) {
                    int c = nt * 8 + tig * 2 + e;
                    float e0 = 0.f, e1 = 0.f;
                    if (c < 49) {
                        e0 = __expf(accS[nt][e]     - m0);
                        e1 = __expf(accS[nt][2 + e] - m1);
                    }
                    accS[nt][e] = e0;     s0 += e0;
                    accS[nt][2 + e] = e1; s1 += e1;
                }
            s0 += __shfl_xor_sync(0xFFFFFFFFu, s0, 1);
            s0 += __shfl_xor_sync(0xFFFFFFFFu, s0, 2);
            s1 += __shfl_xor_sync(0xFFFFFFFFu, s1, 1);
            s1 += __shfl_xor_sync(0xFFFFFFFFu, s1, 2);
            float inv0 = 1.f / s0, inv1 = 1.f / s1;
            __half2* d0 = (__half2*)(Shc + r0 * SH_STRB + tig * 4);
            __half2* d1 = (__half2*)(Shc + (r0 + 8) * SH_STRB + tig * 4);
            #pragma unroll
            for (int nt = 0; nt < 8; nt++) {
                __half2 h0 = (r0 < 49)
                    ? __floats2half2_rn(accS[nt][0] * inv0, accS[nt][1] * inv0)
                    : __floats2half2_rn(0.f, 0.f);
                __half2 h1 = (r0 + 8 < 49)
                    ? __floats2half2_rn(accS[nt][2] * inv1, accS[nt][3] * inv1)
                    : __floats2half2_rn(0.f, 0.f);
                d0[nt * 4] = h0;
                d1[nt * 4] = h1;
            }
        }
        __syncthreads();  // Shc visible; Qc/Kc free for prefetch

        // ---- hoist S fragments into registers (reused by all 8 chunks)
        const int arow = lane & 15;
        const int ak   = (lane >> 4) * 8;
        uint32_t sA[4][4][4];
        #pragma unroll
        for (int ks = 0; ks < 4; ks++)
            #pragma unroll
            for (int mt = 0; mt < 4; mt++)
                LDMATRIX_X4(sA[ks][mt][0], sA[ks][mt][1], sA[ks][mt][2], sA[ks][mt][3],
                            shb + (16 * mt + arow) * SH_STRB + (ks * 16 + ak) * 2);

        // ---- Phase B: O = S V, double-buffered; prefetch next QK at cc==0
        const int kk_l = (lane & 7) + ((lane >> 3) & 1) * 8;
        const int nc_l = 32 * w + ((lane >> 4) << 3);

        for (int cc = 0; cc < 8; cc++) {
            if (cc + 1 < 8) {
                issue_v(base, cc + 1);
                if (cc == 0 && wl == 0) issue_qk(win_base(wi0 + 1));
                asm volatile("cp.async.wait_group 1;" ::: "memory");
            } else {
                asm volatile("cp.async.wait_group 0;" ::: "memory");
            }
            __syncthreads();

            const uint32_t vb = vbb + (cc & 1) * V_BUFB;
            float acc[4][4][4];
            #pragma unroll
            for (int i = 0; i < 4; i++)
                #pragma unroll
                for (int j = 0; j < 4; j++)
                    #pragma unroll
                    for (int q = 0; q < 4; q++) acc[i][j][q] = 0.f;

            #pragma unroll
            for (int ks = 0; ks < 4; ks++) {
                uint32_t bq[2][4];
                #pragma unroll
                for (int nb2 = 0; nb2 < 2; nb2++)
                    LDMATRIX_X4_T(bq[nb2][0], bq[nb2][1], bq[nb2][2], bq[nb2][3],
                                  vb + (ks * 16 + kk_l) * VC_STRB + (nc_l + nb2 * 16) * 2);
                #pragma unroll
                for (int mt = 0; mt < 4; mt++)
                    #pragma unroll
                    for (int nt = 0; nt < 4; nt++)
                        MMA16816(acc[mt][nt], sA[ks][mt],
                                 bq[nt >> 1][(nt & 1) * 2], bq[nt >> 1][(nt & 1) * 2 + 1]);
            }

            #pragma unroll
            for (int mt = 0; mt < 4; mt++) {
                #pragma unroll
                for (int h = 0; h < 2; h++) {
                    int m = 16 * mt + g + h * 8;
                    if (m < 49) {
                        int r = base + (m / 7) * 56 + (m % 7);
                        __half* dst = ao + (size_t)r * CDIM + cc * 128;
                        #pragma unroll
                        for (int nt = 0; nt < 4; nt++) {
                            int n = 32 * w + nt * 8 + tig * 2;
                            *(__half2*)(dst + n) =
                                __floats2half2_rn(acc[mt][nt][h*2+0], acc[mt][nt][h*2+1]);
                        }
                    }
                }
            }
            if (cc < 7) __syncthreads();  // next chunk overwrites the other V buffer
        }
        // no trailing barrier needed: next window's first V write targets buffer 0
        // (disjoint from buffer 1 read at cc==7) and the window-start barrier
        // orders everything else.
    }
}

// ============================================================
// Host launcher
// ============================================================
extern "C" void kernel_launch(void* const* d_in, const int* in_sizes, int n_in,
                              void* d_out, int out_size)
{
    const float* x      = (const float*)d_in[0];
    const float* norm_w = (const float*)d_in[1];
    const float* norm_b = (const float*)d_in[2];
    const float* wq     = (const float*)d_in[3];
    const float* bq     = (const float*)d_in[4];
    const float* wk     = (const float*)d_in[5];
    const float* bk     = (const float*)d_in[6];
    const float* wv     = (const float*)d_in[7];
    const float* bv     = (const float*)d_in[8];
    const float* wr     = (const float*)d_in[9];
    const float* br     = (const float*)d_in[10];
    const float* gamma  = (const float*)d_in[11];
    (void)in_sizes; (void)n_in; (void)out_size;

    float* out  = (float*)d_out;
    float* sem  = out;
    float* xout = out + (size_t)M_ROWS * KSEM;

    __half *xnh, *semh, *kfh, *aoh, *wqkh, *wrh, *wvth, *wch;
    float* bvr;
    cudaGetSymbolAddress((void**)&xnh,  g_xnh);
    cudaGetSymbolAddress((void**)&semh, g_semh);
    cudaGetSymbolAddress((void**)&kfh,  g_kfh);
    cudaGetSymbolAddress((void**)&aoh,  g_aoh);
    cudaGetSymbolAddress((void**)&wqkh, g_wqkh);
    cudaGetSymbolAddress((void**)&wrh,  g_wrh);
    cudaGetSymbolAddress((void**)&wvth, g_wvth);
    cudaGetSymbolAddress((void**)&wch,  g_wch);
    cudaGetSymbolAddress((void**)&bvr,  g_bvr);

    const int SMEM256 = 3 * 49152 + 1024;
    const int SMEM160 = 3 * 36864 + 1024;
    const int SMEM128 = 3 * 32768 + 1024;
    cudaFuncSetAttribute(gemm_h<1, 256, 4>, cudaFuncAttributeMaxDynamicSharedMemorySize, SMEM256);
    cudaFuncSetAttribute(gemm_h<2, 160, 2>, cudaFuncAttributeMaxDynamicSharedMemorySize, SMEM160);
    cudaFuncSetAttribute(gemm_h<4, 128, 2>, cudaFuncAttributeMaxDynamicSharedMemorySize, SMEM128);
    cudaFuncSetAttribute(attn_mma, cudaFuncAttributeMaxDynamicSharedMemorySize, ATTN_SMEM);

    // 0+1) merged prep + LayerNorm
    ln_prep_kernel<<<PREP_BLOCKS + M_ROWS, 256>>>(x, norm_w, norm_b, xnh,
                                                  wq, wk, wr, wv, bv, br, gamma,
                                                  wqkh, wrh, wvth, bvr, semh, kfh);

    // Wc = gamma * Wr @ Wv (half)
    gemm_h<4, 128, 2><<<dim3(8, 8), 256, SMEM128>>>(wrh, wvth, nullptr, nullptr,
                                                    nullptr, wch, nullptr, CDIM, CDIM, nullptr, gamma);

    // 2) merged Q/K projection
    gemm_h<2, 160, 2><<<dim3(2, M_ROWS / 128), 256, SMEM160>>>(xnh, wqkh, bq, bk, sem, semh, kfh,
                                                               300, KSEM, nullptr, nullptr);

    // 3) attention: 2 windows per block
    attn_mma<<<NWIN / 2, 128, ATTN_SMEM>>>(semh, kfh, xnh, aoh);

    // 4) xout = aoh @ Wc^T + bvr + xnh
    gemm_h<1, 256, 4><<<dim3(4, M_ROWS / 128), 256, SMEM256>>>(aoh, wch, bvr, nullptr, xout,
                                                               nullptr, nullptr, CDIM, CDIM, xnh, nullptr);
}